// round 15
// baseline (speedup 1.0000x reference)
#include <cuda_runtime.h>
#include <cstdint>

#define THETA 0.7f

// SMEM (float indices): TWO s buffers (one per cin-half), each
//   [3 sr][132 slot][32 cin tf32, XOR-swizzled] = 12672 floats.
// Epilogue stages D into buffer 0 afterward (64 oc x pitch 132 = 8448 floats).
#define S_BUF_F 12672
#define SMEM_TOTAL (2 * S_BUF_F * 4)

// B fragments pre-baked for direct per-thread LDG.64:
// idx = ((((half*9+tap)*2 + warpN)*4 + nt)*4 + j)*32 + (kb*8 + ocq)
// value = { W'[oc][k], W'[oc][k+4] },  oc = warpN*32+nt*8+ocq,  k = half*32+j*8+kb
__device__ float2 g_Wldg[2 * 9 * 2 * 4 * 4 * 32];

__device__ __forceinline__ int refl(int i, int n) {
    if (i < 0) i = -i;
    if (i >= n) i = 2 * n - 2 - i;
    return i;
}
__device__ __forceinline__ uint32_t tf32r(float v) {
    uint32_t t;
    asm("cvt.rna.tf32.f32 %0, %1;" : "=r"(t) : "f"(v));
    return t;
}
__device__ __forceinline__ void mma1688(float* d, uint32_t a0, uint32_t a1, uint32_t a2,
                                        uint32_t a3, uint32_t b0, uint32_t b1) {
    asm volatile(
        "mma.sync.aligned.m16n8k8.row.col.f32.tf32.tf32.f32 "
        "{%0,%1,%2,%3},{%4,%5,%6,%7},{%8,%9},{%0,%1,%2,%3};"
        : "+f"(d[0]), "+f"(d[1]), "+f"(d[2]), "+f"(d[3])
        : "r"(a0), "r"(a1), "r"(a2), "r"(a3), "r"(b0), "r"(b1));
}

// Effective weight W'[oc][cin][tap] = W - (tap==4)*THETA*sum(taps), tf32-rounded.
__device__ __forceinline__ float wprime(const float* W, int oc, int cin, int tap) {
    const float* base = W + oc * 576 + cin * 9;
    float v = base[tap];
    if (tap == 4) {
        float s = 0.f;
#pragma unroll
        for (int t = 0; t < 9; t++) s += base[t];
        v -= THETA * s;
    }
    return __uint_as_float(tf32r(v));
}

__global__ void prep_w_kernel(const float* __restrict__ W) {
    int idx = blockIdx.x * blockDim.x + threadIdx.x;
    if (idx >= 2 * 9 * 2 * 4 * 4 * 32) return;
    int t = idx;
    const int o  = t & 31; t >>= 5;
    const int j  = t & 3;  t >>= 2;
    const int nt = t & 3;  t >>= 2;
    const int wN = t & 1;  t >>= 1;
    const int tap = t % 9;
    const int half = t / 9;
    const int oc = wN * 32 + nt * 8 + (o & 7);
    const int k0 = half * 32 + j * 8 + (o >> 3);
    g_Wldg[idx] = make_float2(wprime(W, oc, k0, tap), wprime(W, oc, k0 + 4, tap));
}

// Build s = box3x3(reflect-pad x) for one cin-half into sbuf, tf32-rounded,
// zero rows outside image. Branch-free 3-LDG horizontal sum.
__device__ __forceinline__ void build_s(float* __restrict__ sbuf,
                                        const float* __restrict__ x,
                                        int b, int half, int y0, const int* xrg,
                                        int wid, int lane) {
    for (int u = wid; u < 32; u += 8) {
        const int cg = u & 7, chunk = u >> 3;
        const int c = chunk * 32 + lane;
        const int cm = c ? c - 1 : 1;
        const int cp = (c == 127) ? 126 : c + 1;
        float acc[4][3];
#pragma unroll
        for (int i = 0; i < 4; i++)
#pragma unroll
            for (int sr = 0; sr < 3; sr++) acc[i][sr] = 0.f;
#pragma unroll
        for (int i = 0; i < 4; i++) {
            const float* xp = x + (((size_t)b * 64 + half * 32 + cg * 4 + i) << 14);
#pragma unroll
            for (int xr = 0; xr < 5; xr++) {
                const float* rp = xp + xrg[xr] * 128;
                float h = rp[cm] + rp[c] + rp[cp];
                if (xr < 3)            acc[i][xr]     += h;
                if (xr >= 1 && xr < 4) acc[i][xr - 1] += h;
                if (xr >= 2)           acc[i][xr - 2] += h;
            }
        }
#pragma unroll
        for (int sr = 0; sr < 3; sr++) {
            const int vsy = y0 - 1 + sr;
            const bool vr = (vsy >= 0) && (vsy < 128);
            float4 v4;
            v4.x = __uint_as_float(tf32r(vr ? acc[0][sr] : 0.f));
            v4.y = __uint_as_float(tf32r(vr ? acc[1][sr] : 0.f));
            v4.z = __uint_as_float(tf32r(vr ? acc[2][sr] : 0.f));
            v4.w = __uint_as_float(tf32r(vr ? acc[3][sr] : 0.f));
            const int R = sr * 132 + c + 1;
            *(float4*)(sbuf + R * 32 + ((cg << 2) ^ ((R & 7) << 2))) = v4;
        }
    }
}

// MMA over one cin-half: 9 taps x 4 k-groups. A from sbuf (SMEM), B via LDG.64.
__device__ __forceinline__ void mma_half(float d[2][4][4],
                                         const uint32_t* __restrict__ usb,
                                         const float2* __restrict__ wbase,
                                         int half, int warpM, int warpN,
                                         int gr, int gc) {
    for (int dy = 0; dy < 3; dy++) {
#pragma unroll
        for (int dx = 0; dx < 3; dx++) {
            const int tap = dy * 3 + dx;
            const int Rb = dy * 132 + dx + warpM * 32 + gr;
            const int xa = ((4 * dy + dx + gr) & 7) << 2;      // swizzle key (R&7)<<2
            const int abase = Rb * 32;
            const float2* wtap = wbase + (size_t)(((half * 9 + tap) * 2 + warpN)) * 512;
#pragma unroll
            for (int j = 0; j < 4; j++) {
                const int ca0 = (j * 8 + gc) ^ xa;
                const int ca1 = (j * 8 + gc + 4) ^ xa;
                float2 bv[4];
#pragma unroll
                for (int nt = 0; nt < 4; nt++)
                    bv[nt] = __ldg(wtap + (nt * 4 + j) * 32);
                uint32_t a[2][4];
#pragma unroll
                for (int mt = 0; mt < 2; mt++) {
                    const int ab = abase + mt * (16 * 32);
                    a[mt][0] = usb[ab + ca0];
                    a[mt][1] = usb[ab + 8 * 32 + ca0];
                    a[mt][2] = usb[ab + ca1];
                    a[mt][3] = usb[ab + 8 * 32 + ca1];
                }
#pragma unroll
                for (int nt = 0; nt < 4; nt++) {
                    const uint32_t b0 = __float_as_uint(bv[nt].x);
                    const uint32_t b1 = __float_as_uint(bv[nt].y);
#pragma unroll
                    for (int mt = 0; mt < 2; mt++)
                        mma1688(d[mt][nt], a[mt][0], a[mt][1], a[mt][2], a[mt][3], b0, b1);
                }
            }
        }
    }
}

// One block per (output row y0, batch b). 256 threads, 8 warps, 2 blocks/SM.
// Double-buffered s: build h0 | bar | {MMA h0 -> build h1} | bar | MMA h1.
__global__ __launch_bounds__(256, 2)
void conv_mma_kernel(const float* __restrict__ x, float* __restrict__ out) {
    extern __shared__ float sf[];
    float* s0 = sf;
    float* s1 = sf + S_BUF_F;
    const int tid = threadIdx.x, wid = tid >> 5, lane = tid & 31;
    const int warpM = wid & 3, warpN = wid >> 2;
    const int gr = lane >> 2, gc = lane & 3;      // A-frag lanes
    const int kb = lane & 3, ocq = lane >> 2;     // B-frag lanes
    const int y0 = blockIdx.x, b = blockIdx.y;

    float d[2][4][4];
#pragma unroll
    for (int i = 0; i < 2; i++)
#pragma unroll
        for (int j = 0; j < 4; j++)
#pragma unroll
            for (int r = 0; r < 4; r++) d[i][j][r] = 0.f;

    int xrg[5];
#pragma unroll
    for (int i = 0; i < 5; i++) xrg[i] = refl(y0 - 2 + i, 128);

    // Zero-pad slots 0 and 129 of each of the 3 s rows, in BOTH buffers
    // (slots never written by build; read by dx=0/m=0 and dx=2/m=127 taps).
    if (tid < 192) {
        const int sr = tid >> 6, slot = ((tid >> 5) & 1) * 129, cl = tid & 31;
        s0[(sr * 132 + slot) * 32 + cl] = 0.f;
        s1[(sr * 132 + slot) * 32 + cl] = 0.f;
    }

    const float2* wbase = g_Wldg + (size_t)(kb * 8 + ocq);

    build_s(s0, x, b, 0, y0, xrg, wid, lane);
    __syncthreads();

    // Overlap zone: each warp runs MMA h0, then immediately starts build h1
    // (writes s1, which nobody reads yet) — no barrier in between.
    mma_half(d, (const uint32_t*)s0, wbase, 0, warpM, warpN, gr, gc);
    build_s(s1, x, b, 1, y0, xrg, wid, lane);
    __syncthreads();

    mma_half(d, (const uint32_t*)s1, wbase, 1, warpM, warpN, gr, gc);

    // Epilogue: stage D[oc][p] into s0 region (pitch 132, conflict-free).
    // Safe without a barrier: all s0 reads ended before the previous barrier,
    // and staging addresses are per-thread exclusive.
#pragma unroll
    for (int mt = 0; mt < 2; mt++)
#pragma unroll
        for (int nt = 0; nt < 4; nt++)
#pragma unroll
            for (int r = 0; r < 4; r++) {
                const int p = warpM * 32 + mt * 16 + gr + 8 * (r >> 1);
                const int oc = warpN * 32 + nt * 8 + 2 * kb + (r & 1);
                s0[oc * 132 + p] = d[mt][nt][r];
            }
    __syncthreads();
#pragma unroll
    for (int it = 0; it < 32; it++) {
        const int idx = it * 256 + tid;
        const int oc = idx >> 7, p = idx & 127;
        out[(((size_t)b * 64 + oc) << 14) + (size_t)y0 * 128 + p] = s0[oc * 132 + p];
    }
}

extern "C" void kernel_launch(void* const* d_in, const int* in_sizes, int n_in,
                              void* d_out, int out_size) {
    const float* x = (const float*)d_in[0];   // [16,64,128,128]
    const float* W = (const float*)d_in[1];   // [64,64,3,3]
    float* out = (float*)d_out;               // [16,64,128,128]

    prep_w_kernel<<<(2 * 9 * 2 * 4 * 4 * 32 + 255) / 256, 256>>>(W);

    cudaFuncSetAttribute(conv_mma_kernel, cudaFuncAttributeMaxDynamicSharedMemorySize,
                         SMEM_TOTAL);
    dim3 grid(128, 16);
    conv_mma_kernel<<<grid, 256, SMEM_TOTAL>>>(x, out);
}

// round 16
// speedup vs baseline: 1.3864x; 1.3864x over previous
#include <cuda_runtime.h>
#include <cstdint>

#define THETA 0.7f

// SMEM (float indices): one s buffer [4 sr][132 slot][32 cin tf32, XOR-swizzled]
//   = 16896 floats. Epilogue stages D here afterward (64 oc x pitch 260 = 16640).
#define S_BUF_F 16896
#define SMEM_TOTAL (S_BUF_F * 4)

// B fragments pre-baked for direct per-thread LDG.64:
// idx = ((((half*9+tap)*2 + wN)*4 + nt)*4 + j)*32 + (kb*8 + ocq)
// value = { W'[oc][k], W'[oc][k+4] },  oc = wN*32+nt*8+ocq,  k = half*32+j*8+kb
__device__ float2 g_Wldg[2 * 9 * 2 * 4 * 4 * 32];

__device__ __forceinline__ int refl(int i, int n) {
    if (i < 0) i = -i;
    if (i >= n) i = 2 * n - 2 - i;
    return i;
}
__device__ __forceinline__ uint32_t tf32r(float v) {
    uint32_t t;
    asm("cvt.rna.tf32.f32 %0, %1;" : "=r"(t) : "f"(v));
    return t;
}
__device__ __forceinline__ void mma1688(float* d, uint32_t a0, uint32_t a1, uint32_t a2,
                                        uint32_t a3, uint32_t b0, uint32_t b1) {
    asm volatile(
        "mma.sync.aligned.m16n8k8.row.col.f32.tf32.tf32.f32 "
        "{%0,%1,%2,%3},{%4,%5,%6,%7},{%8,%9},{%0,%1,%2,%3};"
        : "+f"(d[0]), "+f"(d[1]), "+f"(d[2]), "+f"(d[3])
        : "r"(a0), "r"(a1), "r"(a2), "r"(a3), "r"(b0), "r"(b1));
}

// Effective weight W'[oc][cin][tap] = W - (tap==4)*THETA*sum(taps), tf32-rounded.
__device__ __forceinline__ float wprime(const float* W, int oc, int cin, int tap) {
    const float* base = W + oc * 576 + cin * 9;
    float v = base[tap];
    if (tap == 4) {
        float s = 0.f;
#pragma unroll
        for (int t = 0; t < 9; t++) s += base[t];
        v -= THETA * s;
    }
    return __uint_as_float(tf32r(v));
}

__global__ void prep_w_kernel(const float* __restrict__ W) {
    int idx = blockIdx.x * blockDim.x + threadIdx.x;
    if (idx >= 2 * 9 * 2 * 4 * 4 * 32) return;
    int t = idx;
    const int o  = t & 31; t >>= 5;
    const int j  = t & 3;  t >>= 2;
    const int nt = t & 3;  t >>= 2;
    const int wN = t & 1;  t >>= 1;
    const int tap = t % 9;
    const int half = t / 9;
    const int oc = wN * 32 + nt * 8 + (o & 7);
    const int k0 = half * 32 + j * 8 + (o >> 3);
    g_Wldg[idx] = make_float2(wprime(W, oc, k0, tap), wprime(W, oc, k0 + 4, tap));
}

// One block per (output-row PAIR y0, batch b). 256 threads, 8 warps, 2 blocks/SM.
// GEMM: M=256 (2 rows x 128 px), N=64 oc, K=576. Warp tile 32M x 64N.
// A from SMEM (single s buffer, clean 3-LDG build), B via per-thread LDG.64.
__global__ __launch_bounds__(256, 2)
void conv_mma_kernel(const float* __restrict__ x, float* __restrict__ out) {
    extern __shared__ float sf[];
    uint32_t* us = (uint32_t*)sf;
    const int tid = threadIdx.x, wid = tid >> 5, lane = tid & 31;
    const int r_out = wid >> 2;          // which of the 2 output rows
    const int wq = wid & 3;              // 32-px group within the row
    const int gr = lane >> 2, gc = lane & 3;      // A-frag lanes
    const int kb = lane & 3, ocq = lane >> 2;     // B-frag lanes
    const int y0 = blockIdx.x, b = blockIdx.y;

    float d[2][8][4];
#pragma unroll
    for (int i = 0; i < 2; i++)
#pragma unroll
        for (int j = 0; j < 8; j++)
#pragma unroll
            for (int r = 0; r < 4; r++) d[i][j][r] = 0.f;

    int xrg[6];
#pragma unroll
    for (int i = 0; i < 6; i++) xrg[i] = refl(y0 * 2 - 2 + i, 128);

    // Zero-pad slots 0 and 129 of each of the 4 s rows (never written by build).
    {
        const int sr = tid >> 6, slot = ((tid >> 5) & 1) * 129, cl = tid & 31;
        sf[(sr * 132 + slot) * 32 + cl] = 0.f;
    }

    const float2* wbase = g_Wldg + (size_t)(kb * 8 + ocq);

    for (int half = 0; half < 2; half++) {
        __syncthreads();   // previous half's s fully consumed

        // Build s = box3x3(reflect-pad x) for rows y0*2-1 .. y0*2+2, tf32,
        // zero rows outside image. Branch-free 3-LDG horizontal sum.
        for (int u = wid; u < 32; u += 8) {
            const int cg = u & 7, chunk = u >> 3;
            const int c = chunk * 32 + lane;
            const int cm = c ? c - 1 : 1;
            const int cp = (c == 127) ? 126 : c + 1;
            float acc[4][4];
#pragma unroll
            for (int i = 0; i < 4; i++)
#pragma unroll
                for (int sr = 0; sr < 4; sr++) acc[i][sr] = 0.f;
#pragma unroll
            for (int i = 0; i < 4; i++) {
                const float* xp = x + (((size_t)b * 64 + half * 32 + cg * 4 + i) << 14);
#pragma unroll
                for (int xr = 0; xr < 6; xr++) {
                    const float* rp = xp + xrg[xr] * 128;
                    float h = rp[cm] + rp[c] + rp[cp];
                    // s row sr sums x rows xrg[sr..sr+2]
#pragma unroll
                    for (int sr = 0; sr < 4; sr++)
                        if (xr >= sr && xr <= sr + 2) acc[i][sr] += h;
                }
            }
#pragma unroll
            for (int sr = 0; sr < 4; sr++) {
                const int vsy = y0 * 2 - 1 + sr;
                const bool vr = (vsy >= 0) && (vsy < 128);
                float4 v4;
                v4.x = __uint_as_float(tf32r(vr ? acc[0][sr] : 0.f));
                v4.y = __uint_as_float(tf32r(vr ? acc[1][sr] : 0.f));
                v4.z = __uint_as_float(tf32r(vr ? acc[2][sr] : 0.f));
                v4.w = __uint_as_float(tf32r(vr ? acc[3][sr] : 0.f));
                const int R = sr * 132 + c + 1;
                *(float4*)(sf + R * 32 + ((cg << 2) ^ ((R & 7) << 2))) = v4;
            }
        }
        __syncthreads();

        // MMA mainloop: 9 taps x 4 k-groups x (2 mt x 8 nt).
        for (int dy = 0; dy < 3; dy++) {
#pragma unroll
            for (int dx = 0; dx < 3; dx++) {
                const int tap = dy * 3 + dx;
                const int srow = r_out + dy;
                const int Rb = srow * 132 + dx + wq * 32 + gr;
                const int xa = ((4 * srow + dx + gr) & 7) << 2;    // swizzle key (R&7)<<2
                const int abase = Rb * 32;
                const float2* wtap = wbase + (size_t)((half * 9 + tap) * 2) * 512;
#pragma unroll
                for (int j = 0; j < 4; j++) {
                    const int ca0 = (j * 8 + gc) ^ xa;
                    const int ca1 = (j * 8 + gc + 4) ^ xa;
                    uint32_t a[2][4];
#pragma unroll
                    for (int mt = 0; mt < 2; mt++) {
                        const int ab = abase + mt * (16 * 32);
                        a[mt][0] = us[ab + ca0];
                        a[mt][1] = us[ab + 8 * 32 + ca0];
                        a[mt][2] = us[ab + ca1];
                        a[mt][3] = us[ab + 8 * 32 + ca1];
                    }
#pragma unroll
                    for (int nt = 0; nt < 8; nt++) {
                        const float2 bv = __ldg(wtap + (nt >> 2) * 512 +
                                                ((nt & 3) * 4 + j) * 32);
                        const uint32_t b0 = __float_as_uint(bv.x);
                        const uint32_t b1 = __float_as_uint(bv.y);
#pragma unroll
                        for (int mt = 0; mt < 2; mt++)
                            mma1688(d[mt][nt], a[mt][0], a[mt][1], a[mt][2], a[mt][3], b0, b1);
                    }
                }
            }
        }
    }

    // Epilogue: stage D[oc][m] (pitch 260, conflict-free), then coalesced STG.
    __syncthreads();
#pragma unroll
    for (int mt = 0; mt < 2; mt++)
#pragma unroll
        for (int nt = 0; nt < 8; nt++)
#pragma unroll
            for (int r = 0; r < 4; r++) {
                const int m = r_out * 128 + wq * 32 + mt * 16 + gr + 8 * (r >> 1);
                const int oc = nt * 8 + 2 * kb + (r & 1);
                sf[oc * 260 + m] = d[mt][nt][r];
            }
    __syncthreads();
#pragma unroll
    for (int it = 0; it < 64; it++) {
        const int idx = it * 256 + tid;
        const int oc = idx >> 8, m = idx & 255;
        out[(((size_t)b * 64 + oc) << 14) + (size_t)(y0 * 2 + (m >> 7)) * 128 + (m & 127)] =
            sf[oc * 260 + m];
    }
}

extern "C" void kernel_launch(void* const* d_in, const int* in_sizes, int n_in,
                              void* d_out, int out_size) {
    const float* x = (const float*)d_in[0];   // [16,64,128,128]
    const float* W = (const float*)d_in[1];   // [64,64,3,3]
    float* out = (float*)d_out;               // [16,64,128,128]

    prep_w_kernel<<<(2 * 9 * 2 * 4 * 4 * 32 + 255) / 256, 256>>>(W);

    cudaFuncSetAttribute(conv_mma_kernel, cudaFuncAttributeMaxDynamicSharedMemorySize,
                         SMEM_TOTAL);
    dim3 grid(64, 16);
    conv_mma_kernel<<<grid, 256, SMEM_TOTAL>>>(x, out);
}